// round 17
// baseline (speedup 1.0000x reference)
#include <cuda_runtime.h>
#include <cuda_bf16.h>
#include <mma.h>
#include <math.h>

#define NN 50000
#define EE 800000
#define BB 64
#define OBSD 128
#define MHD 256
#define NAD 16

using namespace nvcuda;

// ---------------- scratch ----------------
__device__ __nv_bfloat16  g_xb[NN * 128];   // layer activations (bf16)
__device__ __nv_bfloat16  g_h[NN * 128];    // h = x @ W (layers 1/2)
__device__ __nv_bfloat16  g_x8[NN * 8];     // layer-0 input, bf16
__device__ float g_as[NN * 2];
__device__ float g_ad[NN * 2];
__device__ int   g_deg[NN + 1];
__device__ int   g_off[NN + 1];
__device__ int   g_cur[NN];
__device__ int   g_csr[EE];
__device__ float g_pool[BB * 64];

__device__ __forceinline__ float lrelu(float v) { return v > 0.f ? v : 0.2f * v; }

__device__ __forceinline__ void red4(float* p, float a, float b, float c, float d) {
    asm volatile("red.global.add.v4.f32 [%0], {%1,%2,%3,%4};"
                 :: "l"(p), "f"(a), "f"(b), "f"(c), "f"(d) : "memory");
}

// ---- packed 64-bit helpers ----
__device__ __forceinline__ unsigned long long pack2u(unsigned x, float y) {
    unsigned long long r;
    asm("mov.b64 %0, {%1, %2};" : "=l"(r) : "r"(x), "r"(__float_as_uint(y)));
    return r;
}
__device__ __forceinline__ void unpack2u(unsigned long long v, unsigned& x, float& y) {
    unsigned lo, hi;
    asm("mov.b64 {%0, %1}, %2;" : "=r"(lo), "=r"(hi) : "l"(v));
    x = lo; y = __uint_as_float(hi);
}

// bf16 helpers
__device__ __forceinline__ void st_h4(__nv_bfloat16* p, const float* f) {
    uint2 u;
    *reinterpret_cast<__nv_bfloat162*>(&u.x) = __floats2bfloat162_rn(f[0], f[1]);
    *reinterpret_cast<__nv_bfloat162*>(&u.y) = __floats2bfloat162_rn(f[2], f[3]);
    *reinterpret_cast<uint2*>(p) = u;
}
__device__ __forceinline__ void st_h2(__nv_bfloat16* p, float f0, float f1) {
    unsigned u;
    *reinterpret_cast<__nv_bfloat162*>(&u) = __floats2bfloat162_rn(f0, f1);
    *reinterpret_cast<unsigned*>(p) = u;
}
__device__ __forceinline__ void acc_h4u(float* acc, uint2 v, float w) {
    float2 lo = __bfloat1622float2(*reinterpret_cast<__nv_bfloat162*>(&v.x));
    float2 hi = __bfloat1622float2(*reinterpret_cast<__nv_bfloat162*>(&v.y));
    acc[0] += w * lo.x; acc[1] += w * lo.y; acc[2] += w * hi.x; acc[3] += w * hi.y;
}
__device__ __forceinline__ void acc_h8(float* acc, uint4 v, float w) {
    float2 a = __bfloat1622float2(*reinterpret_cast<__nv_bfloat162*>(&v.x));
    float2 b = __bfloat1622float2(*reinterpret_cast<__nv_bfloat162*>(&v.y));
    float2 c = __bfloat1622float2(*reinterpret_cast<__nv_bfloat162*>(&v.z));
    float2 d = __bfloat1622float2(*reinterpret_cast<__nv_bfloat162*>(&v.w));
    acc[0] += w * a.x; acc[1] += w * a.y; acc[2] += w * b.x; acc[3] += w * b.y;
    acc[4] += w * c.x; acc[5] += w * c.y; acc[6] += w * d.x; acc[7] += w * d.y;
}
__device__ __forceinline__ void unpack8(uint4 v, float* f) {
    float2 a = __bfloat1622float2(*reinterpret_cast<__nv_bfloat162*>(&v.x));
    float2 b = __bfloat1622float2(*reinterpret_cast<__nv_bfloat162*>(&v.y));
    float2 c = __bfloat1622float2(*reinterpret_cast<__nv_bfloat162*>(&v.z));
    float2 d = __bfloat1622float2(*reinterpret_cast<__nv_bfloat162*>(&v.w));
    f[0] = a.x; f[1] = a.y; f[2] = b.x; f[3] = b.y;
    f[4] = c.x; f[5] = c.y; f[6] = d.x; f[7] = d.y;
}

// =================== prep0: bf16 x8 copy + alpha0 via folded dots (+pool zero) ===================
__global__ void __launch_bounds__(256) k_prep0(const float* __restrict__ xin,
                                               const float* __restrict__ W0,
                                               const float* __restrict__ asrc,
                                               const float* __restrict__ adst) {
    __shared__ float Wsh[8 * 128];
    __shared__ float wfsh[32];
    __shared__ float wred[256];
    int tid = threadIdx.x;
    if (blockIdx.x == 0) {
        for (int i = tid; i < BB * 64; i += 256) g_pool[i] = 0.f;
    }
    for (int i = tid; i < 8 * 128; i += 256) Wsh[i] = W0[i];
    __syncthreads();
    {
        int d = tid >> 3, e = tid & 7;
        int a = d >> 3, k = d & 7, h = a & 1;
        const float* av = ((a < 2) ? asrc : adst) + h * 64;
        const float* wr = &Wsh[k * 128 + h * 64];
        float s = 0.f;
#pragma unroll
        for (int c = 0; c < 8; c++) s += wr[e + c * 8] * av[e + c * 8];
        wred[tid] = s;
    }
    __syncthreads();
    if (tid < 32) {
        float s = 0.f;
#pragma unroll
        for (int e = 0; e < 8; e++) s += wred[tid * 8 + e];
        wfsh[tid] = s;
    }
    __syncthreads();

    for (int node = blockIdx.x * 256 + tid; node < NN; node += gridDim.x * 256) {
        float4 xa = *reinterpret_cast<const float4*>(&xin[node * 8]);
        float4 xb = *reinterpret_cast<const float4*>(&xin[node * 8 + 4]);
        float xk[8] = {xa.x, xa.y, xa.z, xa.w, xb.x, xb.y, xb.z, xb.w};
        float s0 = 0.f, s1 = 0.f, d0 = 0.f, d1 = 0.f;
#pragma unroll
        for (int k = 0; k < 8; k++) {
            s0 += xk[k] * wfsh[0 * 8 + k];
            s1 += xk[k] * wfsh[1 * 8 + k];
            d0 += xk[k] * wfsh[2 * 8 + k];
            d1 += xk[k] * wfsh[3 * 8 + k];
        }
        *reinterpret_cast<float2*>(&g_as[node * 2]) = make_float2(s0, s1);
        *reinterpret_cast<float2*>(&g_ad[node * 2]) = make_float2(d0, d1);
        uint4 u;
        *reinterpret_cast<__nv_bfloat162*>(&u.x) = __floats2bfloat162_rn(xk[0], xk[1]);
        *reinterpret_cast<__nv_bfloat162*>(&u.y) = __floats2bfloat162_rn(xk[2], xk[3]);
        *reinterpret_cast<__nv_bfloat162*>(&u.z) = __floats2bfloat162_rn(xk[4], xk[5]);
        *reinterpret_cast<__nv_bfloat162*>(&u.w) = __floats2bfloat162_rn(xk[6], xk[7]);
        *reinterpret_cast<uint4*>(&g_x8[node * 8]) = u;
    }
}

// =================== CSR build ===================
__global__ void k_hist(const int* __restrict__ ei) {
    const int4* d4 = reinterpret_cast<const int4*>(ei + EE);
    for (int i = blockIdx.x * blockDim.x + threadIdx.x; i < EE / 8; i += gridDim.x * blockDim.x) {
        int4 a = d4[i * 2];
        int4 b = d4[i * 2 + 1];
        atomicAdd(&g_deg[a.x], 1);
        atomicAdd(&g_deg[a.y], 1);
        atomicAdd(&g_deg[a.z], 1);
        atomicAdd(&g_deg[a.w], 1);
        atomicAdd(&g_deg[b.x], 1);
        atomicAdd(&g_deg[b.y], 1);
        atomicAdd(&g_deg[b.z], 1);
        atomicAdd(&g_deg[b.w], 1);
    }
}
__global__ void k_scan() {
    __shared__ int sh[1024];
    const int PER = 49;
    int tid = threadIdx.x;
    int base = tid * PER;
    int s = 0;
    for (int k = 0; k < PER; k++) {
        int i = base + k;
        if (i < NN) s += g_deg[i];
    }
    sh[tid] = s;
    __syncthreads();
    for (int o = 1; o < 1024; o <<= 1) {
        int t = (tid >= o) ? sh[tid - o] : 0;
        __syncthreads();
        sh[tid] += t;
        __syncthreads();
    }
    int run = sh[tid] - s;
    for (int k = 0; k < PER; k++) {
        int i = base + k;
        if (i < NN) {
            int d = g_deg[i];
            g_off[i] = run;
            g_cur[i] = run;
            run += d;
        }
    }
    if (tid == 0) g_off[NN] = EE;
}
__global__ void k_fill(const int* __restrict__ ei) {
    const int4* s4 = reinterpret_cast<const int4*>(ei);
    const int4* d4 = reinterpret_cast<const int4*>(ei + EE);
    for (int i = blockIdx.x * blockDim.x + threadIdx.x; i < EE / 8; i += gridDim.x * blockDim.x) {
        int4 sa = s4[i * 2];
        int4 da = d4[i * 2];
        int4 sb = s4[i * 2 + 1];
        int4 db = d4[i * 2 + 1];
        int pa0 = atomicAdd(&g_cur[da.x], 1);
        int pa1 = atomicAdd(&g_cur[da.y], 1);
        int pa2 = atomicAdd(&g_cur[da.z], 1);
        int pa3 = atomicAdd(&g_cur[da.w], 1);
        int pb0 = atomicAdd(&g_cur[db.x], 1);
        int pb1 = atomicAdd(&g_cur[db.y], 1);
        int pb2 = atomicAdd(&g_cur[db.z], 1);
        int pb3 = atomicAdd(&g_cur[db.w], 1);
        g_csr[pa0] = sa.x; g_csr[pa1] = sa.y; g_csr[pa2] = sa.z; g_csr[pa3] = sa.w;
        g_csr[pb0] = sb.x; g_csr[pb1] = sb.y; g_csr[pb2] = sb.z; g_csr[pb3] = sb.w;
    }
}

// =================== layer-0 aggregate on 8-dim x (lane-per-edge, 2x unroll) ===================
__global__ void __launch_bounds__(256) k_agg0x(const float* __restrict__ W0,
                                               const float* __restrict__ bias) {
    __shared__ float Wsh[8 * 128];
    int tid = threadIdx.x, lane = tid & 31, wp = tid >> 5;
    for (int i = tid; i < 8 * 128; i += 256) Wsh[i] = W0[i];
    __syncthreads();

    for (int node = blockIdx.x * 8 + wp; node < NN; node += gridDim.x * 8) {
        float2 adp = *reinterpret_cast<const float2*>(&g_ad[node * 2]);
        float ad00 = adp.x, ad01 = adp.y;
        int beg = g_off[node], end = g_off[node + 1];

        float ax0[8], ax1[8];
#pragma unroll
        for (int k = 0; k < 8; k++) { ax0[k] = 0.f; ax1[k] = 0.f; }
        float d0 = 0.f, d1 = 0.f;

        for (int i = beg + lane; i < end; i += 64) {
            bool has2 = (i + 32) < end;
            int s0 = g_csr[i];
            int s1 = has2 ? g_csr[i + 32] : 0;
            float2 a0 = *reinterpret_cast<const float2*>(&g_as[s0 * 2]);
            float2 a1 = *reinterpret_cast<const float2*>(&g_as[s1 * 2]);
            uint4 xv0 = *reinterpret_cast<const uint4*>(&g_x8[s0 * 8]);
            uint4 xv1 = *reinterpret_cast<const uint4*>(&g_x8[s1 * 8]);
            float w00 = __expf(lrelu(a0.x + ad00));
            float w01 = __expf(lrelu(a0.y + ad01));
            float w10 = has2 ? __expf(lrelu(a1.x + ad00)) : 0.f;
            float w11 = has2 ? __expf(lrelu(a1.y + ad01)) : 0.f;
            d0 += w00 + w10; d1 += w01 + w11;
            float x0[8], x1[8];
            unpack8(xv0, x0);
            unpack8(xv1, x1);
#pragma unroll
            for (int k = 0; k < 8; k++) {
                ax0[k] += w00 * x0[k] + w10 * x1[k];
                ax1[k] += w01 * x0[k] + w11 * x1[k];
            }
        }
        if (lane == 0) {   // self loop
            float2 a = *reinterpret_cast<const float2*>(&g_as[node * 2]);
            float w0 = __expf(lrelu(a.x + ad00));
            float w1 = __expf(lrelu(a.y + ad01));
            d0 += w0; d1 += w1;
            uint4 xv = *reinterpret_cast<const uint4*>(&g_x8[node * 8]);
            float xk[8];
            unpack8(xv, xk);
#pragma unroll
            for (int k = 0; k < 8; k++) { ax0[k] += w0 * xk[k]; ax1[k] += w1 * xk[k]; }
        }

#pragma unroll
        for (int o = 16; o > 0; o >>= 1) {
#pragma unroll
            for (int k = 0; k < 8; k++) {
                ax0[k] += __shfl_xor_sync(0xffffffffu, ax0[k], o);
                ax1[k] += __shfl_xor_sync(0xffffffffu, ax1[k], o);
            }
            d0 += __shfl_xor_sync(0xffffffffu, d0, o);
            d1 += __shfl_xor_sync(0xffffffffu, d1, o);
        }
        float inv0 = 1.0f / (d0 + 1e-16f);
        float inv1 = 1.0f / (d1 + 1e-16f);

        int head = lane >> 4;
        float axs[8];
#pragma unroll
        for (int k = 0; k < 8; k++) axs[k] = head ? (ax1[k] * inv1) : (ax0[k] * inv0);

        float o4[4];
#pragma unroll
        for (int v = 0; v < 4; v++) {
            int dim = lane * 4 + v;
            float s = bias[dim];
#pragma unroll
            for (int k = 0; k < 8; k++) s += axs[k] * Wsh[k * 128 + dim];
            o4[v] = s > 0.f ? s : expm1f(s);
        }
        st_h4(&g_xb[(size_t)node * 128 + lane * 4], o4);
    }
}

// =================== tensor-core big GEMM (128 -> HC) via wmma bf16 ===================
template <int HC>
__global__ void __launch_bounds__(256) k_gemm_wmma(const float* __restrict__ W,
                                                   const float* __restrict__ asrc,
                                                   const float* __restrict__ adst) {
    constexpr int MTILE = (HC == 128) ? 64 : 128;
    constexpr int H     = (HC == 128) ? 2 : 1;
    constexpr int XLD   = 136;
    constexpr int WLD   = (HC == 128) ? 136 : 72;
    constexpr int SLD   = 68;

    extern __shared__ char smem[];
    __nv_bfloat16* xs  = reinterpret_cast<__nv_bfloat16*>(smem);
    __nv_bfloat16* Wsh = xs + MTILE * XLD;
    float*         stg = reinterpret_cast<float*>(Wsh + 128 * WLD);

    int tid = threadIdx.x, lane = tid & 31, w = tid >> 5;
    int r = (HC == 128) ? (w >> 1) : w;
    int c = (HC == 128) ? (w & 1) : 0;
    int base = blockIdx.x * MTILE;

    for (int i = tid; i < 128 * HC / 2; i += 256) {
        int k = (i * 2) / HC, n = (i * 2) % HC;
        float2 wv = *reinterpret_cast<const float2*>(&W[k * HC + n]);
        *reinterpret_cast<__nv_bfloat162*>(&Wsh[k * WLD + n]) = __floats2bfloat162_rn(wv.x, wv.y);
    }
    for (int i = tid; i < MTILE * 16; i += 256) {
        int m = i / 16, q = i % 16;
        int node = base + m;
        uint4 v = (node < NN)
            ? *reinterpret_cast<const uint4*>(&g_xb[(size_t)node * 128 + q * 8])
            : make_uint4(0u, 0u, 0u, 0u);
        *reinterpret_cast<uint4*>(&xs[m * XLD + q * 8]) = v;
    }
    __syncthreads();

    wmma::fragment<wmma::accumulator, 16, 16, 16, float> acc[4];
#pragma unroll
    for (int j = 0; j < 4; j++) wmma::fill_fragment(acc[j], 0.f);

#pragma unroll
    for (int k0 = 0; k0 < 8; k0++) {
        wmma::fragment<wmma::matrix_a, 16, 16, 16, __nv_bfloat16, wmma::row_major> af;
        wmma::load_matrix_sync(af, &xs[(r * 16) * XLD + k0 * 16], XLD);
#pragma unroll
        for (int j = 0; j < 4; j++) {
            wmma::fragment<wmma::matrix_b, 16, 16, 16, __nv_bfloat16, wmma::row_major> bf;
            wmma::load_matrix_sync(bf, &Wsh[(k0 * 16) * WLD + c * 64 + j * 16], WLD);
            wmma::mma_sync(acc[j], af, bf, acc[j]);
        }
    }

    float* st = stg + w * 16 * SLD;
#pragma unroll
    for (int j = 0; j < 4; j++)
        wmma::store_matrix_sync(&st[j * 16], acc[j], SLD, wmma::mem_row_major);
    __syncwarp();

    float as_lo = asrc[c * 64 + lane], as_hi = asrc[c * 64 + lane + 32];
    float ad_lo = adst[c * 64 + lane], ad_hi = adst[c * 64 + lane + 32];

#pragma unroll
    for (int i = 0; i < 16; i++) {
        int node = base + r * 16 + i;
        if (node >= NN) break;
        float2 hv = *reinterpret_cast<const float2*>(&st[i * SLD + lane * 2]);
        st_h2(&g_h[(size_t)node * HC + c * 64 + lane * 2], hv.x, hv.y);
        float e0 = st[i * SLD + lane], e1 = st[i * SLD + lane + 32];
        float vs = e0 * as_lo + e1 * as_hi;
        float vd = e0 * ad_lo + e1 * ad_hi;
#pragma unroll
        for (int o = 16; o > 0; o >>= 1) {
            vs += __shfl_down_sync(0xffffffffu, vs, o);
            vd += __shfl_down_sync(0xffffffffu, vd, o);
        }
        if (lane == 0) {
            g_as[node * H + c] = vs;
            g_ad[node * H + c] = vd;
        }
    }
}

// =================== fused softmax-aggregate (2 edges per warp-instruction) ===================
template <int HC, int H, bool ACT, bool POOL>
__global__ void __launch_bounds__(256) k_agg(const float* __restrict__ bias,
                                             const int* __restrict__ batch) {
    constexpr int PL   = HC / 16;        // floats per lane (8 or 4)
    constexpr int ROWB = HC * 2;         // bytes per h row
    __shared__ __align__(16) unsigned long long s_rec[8][32 * H];
    int lane = threadIdx.x & 31, wp = threadIdx.x >> 5;
    int half = lane >> 4, l = lane & 15;
    int hd = (H == 2) ? (l >> 3) : 0;    // head owned by this lane's dims
    const int stride = gridDim.x * 8;
    const char* hb_lane = reinterpret_cast<const char*>(g_h) + l * PL * 2;

    for (int node = blockIdx.x * 8 + wp; node < NN; node += stride) {
        float ad0 = g_ad[node * H];
        float ad1 = (H == 2) ? g_ad[node * H + 1] : 0.f;
        int beg = g_off[node], end = g_off[node + 1];

        float acc[PL];
#pragma unroll
        for (int v = 0; v < PL; v++) acc[v] = 0.f;
        float d0 = 0.f, d1 = 0.f;

        for (int chunk = beg; chunk < end; chunk += 32) {
            int i = chunk + lane;
            if (i < end) {
                int s = g_csr[i];
                unsigned soff = (unsigned)s * ROWB;
                if (H == 2) {
                    float2 a = *reinterpret_cast<const float2*>(&g_as[s * 2]);
                    float w0 = __expf(lrelu(a.x + ad0));
                    float w1 = __expf(lrelu(a.y + ad1));
                    d0 += w0; d1 += w1;
                    *reinterpret_cast<ulonglong2*>(&s_rec[wp][lane * 2]) =
                        make_ulonglong2(pack2u(soff, w0), pack2u(soff, w1));
                } else {
                    float w0 = __expf(lrelu(g_as[s] + ad0));
                    d0 += w0;
                    s_rec[wp][lane] = pack2u(soff, w0);
                }
            }
            __syncwarp();
            int cnt = min(32, end - chunk);
            // two 16-lane halves each process one edge per step: 8 edges per iter
            for (int j = 0; j < cnt; j += 8) {
                unsigned soff[4];
                float    ww[4];
#pragma unroll
                for (int u = 0; u < 4; u++) {
                    int e = j + u * 2 + half;
                    bool valid = e < cnt;
                    int ei = valid ? e : 0;
                    unsigned long long rec = (H == 2) ? s_rec[wp][ei * 2 + hd]
                                                      : s_rec[wp][ei];
                    unpack2u(rec, soff[u], ww[u]);
                    if (!valid) ww[u] = 0.f;
                }
                if (PL == 8) {
                    uint4 hv[4];
#pragma unroll
                    for (int u = 0; u < 4; u++)
                        hv[u] = *reinterpret_cast<const uint4*>(hb_lane + soff[u]);
#pragma unroll
                    for (int u = 0; u < 4; u++) acc_h8(acc, hv[u], ww[u]);
                } else {
                    uint2 hv[4];
#pragma unroll
                    for (int u = 0; u < 4; u++)
                        hv[u] = *reinterpret_cast<const uint2*>(hb_lane + soff[u]);
#pragma unroll
                    for (int u = 0; u < 4; u++) acc_h4u(acc, hv[u], ww[u]);
                }
            }
            __syncwarp();
        }

        // merge the two halves
#pragma unroll
        for (int v = 0; v < PL; v++)
            acc[v] += __shfl_xor_sync(0xffffffffu, acc[v], 16);

        // self loop (half 0 only; acc symmetric after merge but only half 0 outputs)
        float ws = __expf(lrelu(g_as[node * H + hd] + ((H == 2 && hd) ? ad1 : ad0)));
        if (half == 0) {
            unsigned soff = (unsigned)node * ROWB;
            if (PL == 8) {
                uint4 hv = *reinterpret_cast<const uint4*>(hb_lane + soff);
                acc_h8(acc, hv, ws);
            } else {
                uint2 hv = *reinterpret_cast<const uint2*>(hb_lane + soff);
                acc_h4u(acc, hv, ws);
            }
        }

#pragma unroll
        for (int o = 16; o > 0; o >>= 1) {
            d0 += __shfl_xor_sync(0xffffffffu, d0, o);
            if (H == 2) d1 += __shfl_xor_sync(0xffffffffu, d1, o);
        }

        if (half == 0) {
            float dh = (H == 2 && hd) ? d1 : d0;
            float inv = 1.0f / (dh + ws + 1e-16f);

            float outv[PL];
#pragma unroll
            for (int v = 0; v < PL; v++) {
                float t = acc[v] * inv + bias[l * PL + v];
                if (ACT) t = t > 0.f ? t : expm1f(t);
                outv[v] = t;
            }

            if (POOL) {
                // PL == 4 here: one red4 per lane covers dims [l*4, l*4+4)
                int b = batch[node];
                red4(&g_pool[b * 64 + l * 4], outv[0], outv[1], outv[2], outv[3]);
            } else {
                if (PL == 8) {
                    uint4 u;
                    *reinterpret_cast<__nv_bfloat162*>(&u.x) = __floats2bfloat162_rn(outv[0], outv[1]);
                    *reinterpret_cast<__nv_bfloat162*>(&u.y) = __floats2bfloat162_rn(outv[2], outv[3]);
                    *reinterpret_cast<__nv_bfloat162*>(&u.z) = __floats2bfloat162_rn(outv[4], outv[5]);
                    *reinterpret_cast<__nv_bfloat162*>(&u.w) = __floats2bfloat162_rn(outv[6], outv[7]);
                    *reinterpret_cast<uint4*>(&g_xb[(size_t)node * HC + l * 8]) = u;
                } else {
                    uint2 u;
                    *reinterpret_cast<__nv_bfloat162*>(&u.x) = __floats2bfloat162_rn(outv[0], outv[1]);
                    *reinterpret_cast<__nv_bfloat162*>(&u.y) = __floats2bfloat162_rn(outv[2], outv[3]);
                    *reinterpret_cast<uint2*>(&g_xb[(size_t)node * HC + l * 4]) = u;
                }
            }
        }
    }
}

// =================== MLP head ===================
__global__ void k_mlp(const int* __restrict__ batch,
                      const float* __restrict__ obs,
                      const float* __restrict__ Ws1, const float* __restrict__ bs1,
                      const float* __restrict__ lng, const float* __restrict__ lnb,
                      const float* __restrict__ Ws2, const float* __restrict__ bs2,
                      const float* __restrict__ Wa,  const float* __restrict__ ba,
                      const float* __restrict__ Wc,  const float* __restrict__ bc,
                      float* __restrict__ out) {
    __shared__ float comb[64 + OBSD];
    __shared__ float hb[MHD];
    __shared__ float h2[MHD];
    __shared__ float rb[8];
    __shared__ float stats[2];
    __shared__ float s_cnt;

    int b = blockIdx.x;
    int tid = threadIdx.x;

    if (tid == 0) {
        int lo = 0, hi = NN;
        while (lo < hi) { int m = (lo + hi) >> 1; if (batch[m] < b) lo = m + 1; else hi = m; }
        int st = lo; lo = 0; hi = NN;
        while (lo < hi) { int m = (lo + hi) >> 1; if (batch[m] < b + 1) lo = m + 1; else hi = m; }
        s_cnt = (float)(lo - st);
    }
    __syncthreads();

    if (tid < 64)             comb[tid] = g_pool[b * 64 + tid] / fmaxf(s_cnt, 1.0f);
    else if (tid < 64 + OBSD) comb[tid] = obs[b * OBSD + (tid - 64)];
    __syncthreads();

    float s = bs1[tid];
    for (int k = 0; k < 64 + OBSD; k++) s += comb[k] * Ws1[k * MHD + tid];

    float v = s;
#pragma unroll
    for (int o = 16; o > 0; o >>= 1) v += __shfl_down_sync(0xffffffffu, v, o);
    if ((tid & 31) == 0) rb[tid >> 5] = v;
    __syncthreads();
    if (tid == 0) { float t = 0.f; for (int w = 0; w < 8; w++) t += rb[w]; stats[0] = t / MHD; }
    __syncthreads();
    float mu = stats[0];
    float dv = s - mu;
    v = dv * dv;
#pragma unroll
    for (int o = 16; o > 0; o >>= 1) v += __shfl_down_sync(0xffffffffu, v, o);
    if ((tid & 31) == 0) rb[tid >> 5] = v;
    __syncthreads();
    if (tid == 0) { float t = 0.f; for (int w = 0; w < 8; w++) t += rb[w]; stats[1] = t / MHD; }
    __syncthreads();

    float hn = dv * rsqrtf(stats[1] + 1e-5f) * lng[tid] + lnb[tid];
    hb[tid] = fmaxf(hn, 0.f);
    __syncthreads();

    float s2 = bs2[tid];
    for (int k = 0; k < MHD; k++) s2 += hb[k] * Ws2[k * MHD + tid];
    h2[tid] = fmaxf(s2, 0.f);
    __syncthreads();

    if (tid < NAD) {
        float t = ba[tid];
        for (int k = 0; k < MHD; k++) t += h2[k] * Wa[k * NAD + tid];
        out[b * NAD + tid] = t;
    }
    if (tid == NAD) {
        float t = bc[0];
        for (int k = 0; k < MHD; k++) t += h2[k] * Wc[k];
        out[BB * NAD + b] = t;
    }
}

// =================== launch ===================
static inline int gs(long long n) { return (int)((n + 255) / 256); }

extern "C" void kernel_launch(void* const* d_in, const int* in_sizes, int n_in,
                              void* d_out, int out_size) {
    const float* obs   = (const float*)d_in[0];
    const float* nf    = (const float*)d_in[1];
    const int*   ei    = (const int*)  d_in[2];
    const int*   batch = (const int*)  d_in[3];
    const float* W0 = (const float*)d_in[4];
    const float* as0 = (const float*)d_in[5];
    const float* ad0 = (const float*)d_in[6];
    const float* b0  = (const float*)d_in[7];
    const float* W1 = (const float*)d_in[8];
    const float* as1 = (const float*)d_in[9];
    const float* ad1 = (const float*)d_in[10];
    const float* b1  = (const float*)d_in[11];
    const float* W2 = (const float*)d_in[12];
    const float* as2 = (const float*)d_in[13];
    const float* ad2 = (const float*)d_in[14];
    const float* b2  = (const float*)d_in[15];
    const float* Ws1 = (const float*)d_in[16];
    const float* bs1 = (const float*)d_in[17];
    const float* lng = (const float*)d_in[18];
    const float* lnb = (const float*)d_in[19];
    const float* Ws2 = (const float*)d_in[20];
    const float* bs2 = (const float*)d_in[21];
    const float* Wa  = (const float*)d_in[22];
    const float* ba  = (const float*)d_in[23];
    const float* Wc  = (const float*)d_in[24];
    const float* bc  = (const float*)d_in[25];
    float* out = (float*)d_out;

    void *p_deg;
    cudaGetSymbolAddress(&p_deg, g_deg);

    const int SM128 = (64 * 136 + 128 * 136) * 2 + 8 * 16 * 68 * 4;   // 87040
    const int SM64  = (128 * 136 + 128 * 72) * 2 + 8 * 16 * 68 * 4;   // 88064
    cudaFuncSetAttribute(k_gemm_wmma<128>, cudaFuncAttributeMaxDynamicSharedMemorySize, SM128);
    cudaFuncSetAttribute(k_gemm_wmma<64>,  cudaFuncAttributeMaxDynamicSharedMemorySize, SM64);

    cudaStream_t s2;
    cudaEvent_t evF, evJ;
    cudaStreamCreateWithFlags(&s2, cudaStreamNonBlocking);
    cudaEventCreateWithFlags(&evF, cudaEventDisableTiming);
    cudaEventCreateWithFlags(&evJ, cudaEventDisableTiming);

    cudaMemsetAsync(p_deg, 0, (NN + 1) * sizeof(int));

    cudaEventRecord(evF, 0);
    cudaStreamWaitEvent(s2, evF, 0);
    k_prep0<<<196, 256, 0, s2>>>(nf, W0, as0, ad0);      // side stream: alpha0 + bf16 x8 + pool zero

    k_hist<<<gs(EE / 8), 256>>>(ei);                      // main stream: CSR chain
    k_scan<<<1, 1024>>>();
    k_fill<<<gs(EE / 8), 256>>>(ei);

    cudaEventRecord(evJ, s2);
    cudaStreamWaitEvent(0, evJ, 0);                       // join before agg0x

    const int AGGB = 1563;

    k_agg0x<<<AGGB, 256>>>(W0, b0);
    k_gemm_wmma<128><<<782, 256, SM128>>>(W1, as1, ad1);
    k_agg<128, 2, true, false><<<AGGB, 256>>>(b1, nullptr);
    k_gemm_wmma<64><<<391, 256, SM64>>>(W2, as2, ad2);
    k_agg<64, 1, false, true><<<AGGB, 256>>>(b2, batch);
    k_mlp<<<BB, MHD>>>(batch, obs, Ws1, bs1, lng, lnb, Ws2, bs2, Wa, ba, Wc, bc, out);
}